// round 7
// baseline (speedup 1.0000x reference)
#include <cuda_runtime.h>
#include <cstdint>
#include <cstddef>

// ---------------------------------------------------------------------------
// DARTS-RNN persistent kernel, fp32, FFMA2 (fma.rn.f32x2) inner product.
// 128 CTAs = 4 M-tiles(64 rows) x 32 col-tiles(16 s-cols). Grid barrier
// between DAG levels. States in __device__ scratch; .cg for coherence.
// ---------------------------------------------------------------------------

#define TT    400
#define BB    256
#define NH    512
#define NI    512
#define NCTA  128
#define NTHR  256          // 8 warps; thread tile = 2 rows x 2 s-cols (c & h)
#define KT    32           // K chunk
#define APAD  66           // As[k][row], padded (66*4=264B rows: 8B-aligned)
#define BPAD  68           // Bs[k][dup-col], padded (68*4=272B rows: 16B-aligned)
#define WSZ   (512*1024)   // elements per Ws[i]

typedef unsigned long long u64;

__device__ float    g_state[9][BB * NH];   // s0..s8
__device__ float    g_h[BB * NH];          // h_prev (mean of previous step)
__device__ unsigned g_count;
__device__ unsigned g_sense;

// ---- packed f32x2 helpers -------------------------------------------------
__device__ __forceinline__ u64 f2fma(u64 a, u64 b, u64 c) {
    u64 d;
    asm("fma.rn.f32x2 %0, %1, %2, %3;" : "=l"(d) : "l"(a), "l"(b), "l"(c));
    return d;
}
__device__ __forceinline__ void upk2(u64 v, float& x, float& y) {
    asm("mov.b64 {%0,%1}, %2;" : "=f"(x), "=f"(y) : "l"(v));
}

// ---- grid barrier (sense-reversing; init kernel resets state each launch) -
__device__ __forceinline__ void gbar(unsigned& sense) {
    __syncthreads();
    if (threadIdx.x == 0) {
        sense ^= 1u;
        __threadfence();                       // release this CTA's writes
        if (atomicAdd(&g_count, 1u) == NCTA - 1u) {
            atomicExch(&g_count, 0u);
            __threadfence();                   // reset visible before flag
            atomicExch(&g_sense, sense);
        } else {
            while (*((volatile unsigned*)&g_sense) != sense) { }
        }
        __threadfence();                       // acquire
    }
    __syncthreads();
}

// ---- staging --------------------------------------------------------------
// A: 64 rows x KT k from global (row stride 512), stored transposed As[k][row].
// B: KT k x 32 out-cols (16 c-cols at c0, 16 h-cols at 512+c0) from W[k][1024],
//    stored duplicated: Bs[k][2j,2j+1] = w_cj ; Bs[k][32+2j,32+2j+1] = w_hj.
__device__ __forceinline__ void stage_load(
    const float* __restrict__ A1, const float* __restrict__ A2,
    const float* __restrict__ W,
    int mrow0, int c0, int k0, int tid,
    float4 pa[2], float4& pb)
{
    const float* base = A1;
    int kk0 = k0;
    if (A2 != nullptr && k0 >= 512) { base = A2; kk0 = k0 - 512; }
#pragma unroll
    for (int i = 0; i < 2; i++) {
        int fid = tid + i * NTHR;              // 0..511
        int r = fid >> 3, k4 = fid & 7;
        pa[i] = __ldcg((const float4*)(base + (size_t)(mrow0 + r) * 512 + kk0 + (k4 << 2)));
    }
    int kk = tid >> 3, q = tid & 7;
    int col = (q < 4) ? (c0 + (q << 2)) : (512 + c0 + ((q - 4) << 2));
    pb = __ldg((const float4*)(W + (size_t)(k0 + kk) * 1024 + col));
}

__device__ __forceinline__ void stage_store(
    const float4 pa[2], const float4 pb, int tid,
    float (*As)[APAD], float (*Bs)[BPAD])
{
#pragma unroll
    for (int i = 0; i < 2; i++) {
        int fid = tid + i * NTHR;
        int r = fid >> 3, k4 = fid & 7;
        As[(k4 << 2) + 0][r] = pa[i].x;
        As[(k4 << 2) + 1][r] = pa[i].y;
        As[(k4 << 2) + 2][r] = pa[i].z;
        As[(k4 << 2) + 3][r] = pa[i].w;
    }
    int kk = tid >> 3, q = tid & 7;
    float* d = &Bs[kk][q << 3];                // base = 8q works for c and h halves
    *(float4*)(d)     = make_float4(pb.x, pb.x, pb.y, pb.y);
    *(float4*)(d + 4) = make_float4(pb.z, pb.z, pb.w, pb.w);
}

// inner product: acc[0..1] = c cols {2cg,2cg+1}, acc[2..3] = h cols; each acc
// is an f32x2 over the thread's row pair {2rg, 2rg+1}.
__device__ __forceinline__ void compute_chunk(
    const float (*As)[APAD], const float (*Bs)[BPAD],
    int rg, int cg, u64 acc[4])
{
#pragma unroll 8
    for (int k = 0; k < KT; k++) {
        u64 av = *(const u64*)&As[k][rg << 1];
        ulonglong2 bc = *(const ulonglong2*)&Bs[k][cg << 2];
        ulonglong2 bh = *(const ulonglong2*)&Bs[k][32 + (cg << 2)];
        acc[0] = f2fma(av, bc.x, acc[0]);
        acc[1] = f2fma(av, bc.y, acc[1]);
        acc[2] = f2fma(av, bh.x, acc[2]);
        acc[3] = f2fma(av, bh.y, acc[3]);
    }
}

// act: 0=tanh 1=relu 2=sigmoid 3=identity
__device__ __forceinline__ float gate(int act, float c, float h, float sp) {
    float g = 1.0f / (1.0f + __expf(-c));
    float a;
    switch (act) {
        case 0:  a = tanhf(h); break;
        case 1:  a = fmaxf(h, 0.0f); break;
        case 2:  a = 1.0f / (1.0f + __expf(-h)); break;
        default: a = h; break;
    }
    return sp + g * (a - sp);
}

// One DAG node: SD = SP + sigmoid(c) * (act(h) - SP), [c|h] = A @ W.
// A = [A1 ; A2] rows-K concat when A2 != nullptr (s0 only, nchunk=32).
__device__ __forceinline__ void do_node(
    const float* __restrict__ A1, const float* __restrict__ A2,
    const float* __restrict__ W,
    const float* __restrict__ SP, float* __restrict__ SD,
    int act, int nchunk, int mrow0, int c0,
    float (*smA)[KT][APAD], float (*smB)[KT][BPAD],
    float* macc)                                // nullptr for s0
{
    int tid = threadIdx.x;
    int cg = tid & 7, rg = tid >> 3;
    u64 acc[4] = {0ull, 0ull, 0ull, 0ull};
    float4 pa[2]; float4 pb;

    __syncthreads();                            // protect smem vs previous node
    stage_load(A1, A2, W, mrow0, c0, 0, tid, pa, pb);
    stage_store(pa, pb, tid, smA[0], smB[0]);
    __syncthreads();

#pragma unroll 1
    for (int ch = 0; ch < nchunk; ch++) {
        if (ch + 1 < nchunk)
            stage_load(A1, A2, W, mrow0, c0, (ch + 1) * KT, tid, pa, pb);
        compute_chunk(smA[ch & 1], smB[ch & 1], rg, cg, acc);
        if (ch + 1 < nchunk) {
            stage_store(pa, pb, tid, smA[(ch + 1) & 1], smB[(ch + 1) & 1]);
            __syncthreads();
        }
    }

    // epilogue (thread tile: rows {2rg,2rg+1}, cols {c0+2cg, c0+2cg+1})
    float cc[2][2], hh[2][2];                   // [col][row]
    upk2(acc[0], cc[0][0], cc[0][1]);
    upk2(acc[1], cc[1][0], cc[1][1]);
    upk2(acc[2], hh[0][0], hh[0][1]);
    upk2(acc[3], hh[1][0], hh[1][1]);
    int colg = c0 + (cg << 1);
#pragma unroll
    for (int r = 0; r < 2; r++) {
        int row = mrow0 + (rg << 1) + r;
        float2 sp = __ldcg((const float2*)(SP + (size_t)row * NH + colg));
        float v0 = gate(act, cc[0][r], hh[0][r], sp.x);
        float v1 = gate(act, cc[1][r], hh[1][r], sp.y);
        __stcg((float2*)(SD + (size_t)row * NH + colg), make_float2(v0, v1));
        if (macc) { macc[r * 2 + 0] += v0; macc[r * 2 + 1] += v1; }
    }
}

// ---------------------------------------------------------------------------
__global__ void __launch_bounds__(NTHR, 1)
rnn_persist(const float* __restrict__ x,
            const float* __restrict__ W0,
            const float* __restrict__ Ws,
            float* __restrict__ out)
{
    __shared__ __align__(16) float smA[2][KT][APAD];
    __shared__ __align__(16) float smB[2][KT][BPAD];

    int bid = blockIdx.x;
    int mrow0 = (bid >> 5) * 64;
    int c0 = (bid & 31) * 16;
    int tid = threadIdx.x;
    int cg = tid & 7, rg = tid >> 3;
    unsigned sense = 0;                         // init kernel resets g_sense=0

#pragma unroll 1
    for (int t = 0; t < TT; t++) {
        const float* xt = x + (size_t)t * BB * NI;
        float macc[4] = {0.f, 0.f, 0.f, 0.f};

        // s0: [c|h] = concat(x_t, h_prev) @ W0 ; gate vs h_prev, act=tanh
        do_node(xt, g_h, W0, g_h, g_state[0], 0, 32, mrow0, c0, smA, smB, nullptr);
        gbar(sense);
        // L1: s1 = tanh-node(s0, Ws0)
        do_node(g_state[0], nullptr, Ws + 0 * WSZ, g_state[0], g_state[1], 0, 16, mrow0, c0, smA, smB, macc);
        gbar(sense);
        // L2: s2=relu(s1,Ws1), s3=relu(s1,Ws2), s4=id(s1,Ws3)
        do_node(g_state[1], nullptr, Ws + 1 * WSZ, g_state[1], g_state[2], 1, 16, mrow0, c0, smA, smB, macc);
        do_node(g_state[1], nullptr, Ws + 2 * WSZ, g_state[1], g_state[3], 1, 16, mrow0, c0, smA, smB, macc);
        do_node(g_state[1], nullptr, Ws + 3 * WSZ, g_state[1], g_state[4], 3, 16, mrow0, c0, smA, smB, macc);
        gbar(sense);
        // L3: s5=tanh(s2,Ws4), s7=tanh(s3,Ws6)
        do_node(g_state[2], nullptr, Ws + 4 * WSZ, g_state[2], g_state[5], 0, 16, mrow0, c0, smA, smB, macc);
        do_node(g_state[3], nullptr, Ws + 6 * WSZ, g_state[3], g_state[7], 0, 16, mrow0, c0, smA, smB, macc);
        gbar(sense);
        // L4: s6=sigmoid(s5,Ws5), s8=relu(s5,Ws7)
        do_node(g_state[5], nullptr, Ws + 5 * WSZ, g_state[5], g_state[6], 2, 16, mrow0, c0, smA, smB, macc);
        do_node(g_state[5], nullptr, Ws + 7 * WSZ, g_state[5], g_state[8], 1, 16, mrow0, c0, smA, smB, macc);

        // mean of s1..s8 -> hiddens[t], g_h (and h_last at t=TT-1)
        int colg = c0 + (cg << 1);
#pragma unroll
        for (int r = 0; r < 2; r++) {
            int row = mrow0 + (rg << 1) + r;
            float2 mv = make_float2(macc[r * 2] * 0.125f, macc[r * 2 + 1] * 0.125f);
            __stcg((float2*)(g_h + (size_t)row * NH + colg), mv);
            *(float2*)(out + (size_t)t * BB * NH + (size_t)row * NH + colg) = mv;
            if (t == TT - 1)
                *(float2*)(out + (size_t)TT * BB * NH + (size_t)row * NH + colg) = mv;
        }
        gbar(sense);                            // publish g_h for next step
    }
}

__global__ void rnn_init(const float* __restrict__ hidden) {
    int i = blockIdx.x * blockDim.x + threadIdx.x;
    if (i < BB * NH) g_h[i] = hidden[i];
    if (i == 0) { g_count = 0u; g_sense = 0u; }
}

extern "C" void kernel_launch(void* const* d_in, const int* in_sizes, int n_in,
                              void* d_out, int out_size) {
    (void)in_sizes; (void)n_in; (void)out_size;
    const float* x   = (const float*)d_in[0];   // [400,256,512]
    const float* hid = (const float*)d_in[1];   // [1,256,512]
    const float* W0  = (const float*)d_in[2];   // [1024,1024]
    const float* Ws  = (const float*)d_in[3];   // [8,512,1024]
    float* out = (float*)d_out;                 // hiddens [400,256,512] ++ h_last [1,256,512]

    rnn_init<<<(BB * NH + 255) / 256, 256>>>(hid);
    rnn_persist<<<NCTA, NTHR>>>(x, W0, Ws, out);
}

// round 8
// speedup vs baseline: 1.3560x; 1.3560x over previous
#include <cuda_runtime.h>
#include <cstdint>
#include <cstddef>

// ---------------------------------------------------------------------------
// DARTS-RNN persistent kernel, fp32, FFMA2 inner product, v2.
// 128 CTAs = 4 M-tiles(64 rows) x 32 col-tiles(16 s-cols); 128 threads/CTA;
// thread tile 2 rows x 4 s-cols (16 GEMM outputs, 8 f32x2 accumulators).
// A transposed (non-dup) in smem, B natural in smem, A-dup via ALU movs.
// One __syncthreads per K-chunk. Grid barrier between DAG levels.
// ---------------------------------------------------------------------------

#define TT    400
#define BB    256
#define NH    512
#define NCTA  128
#define NTHR  128
#define KT    32
#define APAD  66           // As[k][row(64)+pad]; 264B row stride (8B mult)
#define BPAD  36           // Bs[k][col(32)+pad]; 144B row stride (16B mult)
#define WSZ   (512*1024)

typedef unsigned long long u64;

__device__ float    g_state[9][BB * NH];   // s0..s8
__device__ float    g_h[BB * NH];          // h_prev
__device__ unsigned g_count;
__device__ unsigned g_sense;

// ---- packed f32x2 helpers -------------------------------------------------
__device__ __forceinline__ u64 f2fma(u64 a, u64 b, u64 c) {
    u64 d;
    asm("fma.rn.f32x2 %0, %1, %2, %3;" : "=l"(d) : "l"(a), "l"(b), "l"(c));
    return d;
}
__device__ __forceinline__ u64 dup2(float x) {
    u64 d;
    asm("mov.b64 %0, {%1, %1};" : "=l"(d) : "f"(x));
    return d;
}
__device__ __forceinline__ void upk2(u64 v, float& x, float& y) {
    asm("mov.b64 {%0,%1}, %2;" : "=f"(x), "=f"(y) : "l"(v));
}

// ---- grid barrier (sense-reversing; init kernel resets state) -------------
__device__ __forceinline__ void gbar(unsigned& sense) {
    __syncthreads();
    if (threadIdx.x == 0) {
        sense ^= 1u;
        __threadfence();
        if (atomicAdd(&g_count, 1u) == NCTA - 1u) {
            atomicExch(&g_count, 0u);
            __threadfence();
            atomicExch(&g_sense, sense);
        } else {
            while (*((volatile unsigned*)&g_sense) != sense) { }
        }
        __threadfence();
    }
    __syncthreads();
}

// ---- staging --------------------------------------------------------------
// A: 64 rows x KT k (row-major global, stride 512) -> As[k][row] transposed.
// B: KT k x 32 cols (16 c-cols at c0, 16 h-cols at 512+c0) -> Bs[k][0..31].
__device__ __forceinline__ void stage_load(
    const float* __restrict__ A1, const float* __restrict__ A2,
    const float* __restrict__ W,
    int mrow0, int c0, int k0, int tid,
    float4 pa[4], float4 pb[2])
{
    const float* base = A1;
    int kk0 = k0;
    if (A2 != nullptr && k0 >= 512) { base = A2; kk0 = k0 - 512; }
#pragma unroll
    for (int i = 0; i < 4; i++) {
        int fid = tid + i * NTHR;              // 0..511
        int r = fid >> 3, k4 = fid & 7;
        pa[i] = __ldcg((const float4*)(base + (size_t)(mrow0 + r) * 512 + kk0 + (k4 << 2)));
    }
#pragma unroll
    for (int i = 0; i < 2; i++) {
        int fid = tid + i * NTHR;              // 0..255
        int kk = fid >> 3, q = fid & 7;
        int col = (q < 4) ? (c0 + (q << 2)) : (512 + c0 + ((q - 4) << 2));
        pb[i] = __ldg((const float4*)(W + (size_t)(k0 + kk) * 1024 + col));
    }
}

__device__ __forceinline__ void stage_store(
    const float4 pa[4], const float4 pb[2], int tid,
    float (*As)[APAD], float (*Bs)[BPAD])
{
#pragma unroll
    for (int i = 0; i < 4; i++) {
        int fid = tid + i * NTHR;
        int r = fid >> 3, k4 = fid & 7;
        As[(k4 << 2) + 0][r] = pa[i].x;
        As[(k4 << 2) + 1][r] = pa[i].y;
        As[(k4 << 2) + 2][r] = pa[i].z;
        As[(k4 << 2) + 3][r] = pa[i].w;
    }
#pragma unroll
    for (int i = 0; i < 2; i++) {
        int fid = tid + i * NTHR;
        int kk = fid >> 3, q = fid & 7;
        *(float4*)&Bs[kk][q << 2] = pb[i];     // local col 4q (c: q<4, h: q>=4)
    }
}

// inner product: acc[p] (p 0..3) = row 2rg, col-pairs {c01,c23,h01,h23};
// acc[4..7] = row 2rg+1, same col-pairs. Cols are s-cols 4cg..4cg+3.
__device__ __forceinline__ void compute_chunk(
    const float (*As)[APAD], const float (*Bs)[BPAD],
    int rg, int cg, u64 acc[8])
{
#pragma unroll 8
    for (int k = 0; k < KT; k++) {
        float2 av = *(const float2*)&As[k][rg << 1];       // rows 2rg,2rg+1
        ulonglong2 bc = *(const ulonglong2*)&Bs[k][cg << 2];       // 4 c-cols
        ulonglong2 bh = *(const ulonglong2*)&Bs[k][16 + (cg << 2)];// 4 h-cols
        u64 a0 = dup2(av.x), a1 = dup2(av.y);
        acc[0] = f2fma(a0, bc.x, acc[0]);
        acc[1] = f2fma(a0, bc.y, acc[1]);
        acc[2] = f2fma(a0, bh.x, acc[2]);
        acc[3] = f2fma(a0, bh.y, acc[3]);
        acc[4] = f2fma(a1, bc.x, acc[4]);
        acc[5] = f2fma(a1, bc.y, acc[5]);
        acc[6] = f2fma(a1, bh.x, acc[6]);
        acc[7] = f2fma(a1, bh.y, acc[7]);
    }
}

// act: 0=tanh 1=relu 2=sigmoid 3=identity
__device__ __forceinline__ float gate(int act, float c, float h, float sp) {
    float g = 1.0f / (1.0f + __expf(-c));
    float a;
    switch (act) {
        case 0:  a = tanhf(h); break;
        case 1:  a = fmaxf(h, 0.0f); break;
        case 2:  a = 1.0f / (1.0f + __expf(-h)); break;
        default: a = h; break;
    }
    return sp + g * (a - sp);
}

// One DAG node: SD = SP + sigmoid(c) * (act(h) - SP), [c|h] = A @ W.
__device__ __forceinline__ void do_node(
    const float* __restrict__ A1, const float* __restrict__ A2,
    const float* __restrict__ W,
    const float* __restrict__ SP, float* __restrict__ SD,
    int act, int nchunk, int mrow0, int c0,
    float (*smA)[KT][APAD], float (*smB)[KT][BPAD],
    float* macc)
{
    int tid = threadIdx.x;
    int cg = tid & 3, rg = tid >> 2;           // 4 col-groups x 32 row-groups
    u64 acc[8] = {0,0,0,0,0,0,0,0};
    float4 pa[4]; float4 pb[2];

    stage_load(A1, A2, W, mrow0, c0, 0, tid, pa, pb);
    __syncthreads();                            // retire prev node's smem reads
    stage_store(pa, pb, tid, smA[0], smB[0]);

#pragma unroll 1
    for (int ch = 0; ch < nchunk; ch++) {
        if (ch + 1 < nchunk)
            stage_load(A1, A2, W, mrow0, c0, (ch + 1) * KT, tid, pa, pb);
        __syncthreads();                        // buf[ch] visible; buf[ch+1] free
        if (ch + 1 < nchunk)
            stage_store(pa, pb, tid, smA[(ch + 1) & 1], smB[(ch + 1) & 1]);
        compute_chunk(smA[ch & 1], smB[ch & 1], rg, cg, acc);
    }

    // epilogue: rows {2rg,2rg+1}, s-cols {c0+4cg .. +3}
    float cv[2][4], hv[2][4];
    upk2(acc[0], cv[0][0], cv[0][1]); upk2(acc[1], cv[0][2], cv[0][3]);
    upk2(acc[2], hv[0][0], hv[0][1]); upk2(acc[3], hv[0][2], hv[0][3]);
    upk2(acc[4], cv[1][0], cv[1][1]); upk2(acc[5], cv[1][2], cv[1][3]);
    upk2(acc[6], hv[1][0], hv[1][1]); upk2(acc[7], hv[1][2], hv[1][3]);
    int colg = c0 + (cg << 2);
#pragma unroll
    for (int r = 0; r < 2; r++) {
        int row = mrow0 + (rg << 1) + r;
        float4 sp = __ldcg((const float4*)(SP + (size_t)row * NH + colg));
        float4 v;
        v.x = gate(act, cv[r][0], hv[r][0], sp.x);
        v.y = gate(act, cv[r][1], hv[r][1], sp.y);
        v.z = gate(act, cv[r][2], hv[r][2], sp.z);
        v.w = gate(act, cv[r][3], hv[r][3], sp.w);
        __stcg((float4*)(SD + (size_t)row * NH + colg), v);
        if (macc) {
            macc[r * 4 + 0] += v.x; macc[r * 4 + 1] += v.y;
            macc[r * 4 + 2] += v.z; macc[r * 4 + 3] += v.w;
        }
    }
}

// ---------------------------------------------------------------------------
__global__ void __launch_bounds__(NTHR, 1)
rnn_persist(const float* __restrict__ x,
            const float* __restrict__ W0,
            const float* __restrict__ Ws,
            float* __restrict__ out)
{
    __shared__ __align__(16) float smA[2][KT][APAD];
    __shared__ __align__(16) float smB[2][KT][BPAD];

    int bid = blockIdx.x;
    int mrow0 = (bid >> 5) * 64;
    int c0 = (bid & 31) * 16;
    int tid = threadIdx.x;
    int cg = tid & 3, rg = tid >> 2;
    unsigned sense = 0;

#pragma unroll 1
    for (int t = 0; t < TT; t++) {
        const float* xt = x + (size_t)t * BB * NH;
        float macc[8] = {0.f,0.f,0.f,0.f,0.f,0.f,0.f,0.f};

        // s0: [c|h] = concat(x_t, h_prev) @ W0, gate vs h_prev (tanh)
        do_node(xt, g_h, W0, g_h, g_state[0], 0, 32, mrow0, c0, smA, smB, nullptr);
        gbar(sense);
        // L1: s1 = tanh-node(s0, Ws0)
        do_node(g_state[0], nullptr, Ws + 0 * WSZ, g_state[0], g_state[1], 0, 16, mrow0, c0, smA, smB, macc);
        gbar(sense);
        // L2: s2=relu(s1,Ws1), s3=relu(s1,Ws2), s4=id(s1,Ws3)
        do_node(g_state[1], nullptr, Ws + 1 * WSZ, g_state[1], g_state[2], 1, 16, mrow0, c0, smA, smB, macc);
        do_node(g_state[1], nullptr, Ws + 2 * WSZ, g_state[1], g_state[3], 1, 16, mrow0, c0, smA, smB, macc);
        do_node(g_state[1], nullptr, Ws + 3 * WSZ, g_state[1], g_state[4], 3, 16, mrow0, c0, smA, smB, macc);
        gbar(sense);
        // L3: s5=tanh(s2,Ws4), s7=tanh(s3,Ws6)
        do_node(g_state[2], nullptr, Ws + 4 * WSZ, g_state[2], g_state[5], 0, 16, mrow0, c0, smA, smB, macc);
        do_node(g_state[3], nullptr, Ws + 6 * WSZ, g_state[3], g_state[7], 0, 16, mrow0, c0, smA, smB, macc);
        gbar(sense);
        // L4: s6=sigmoid(s5,Ws5), s8=relu(s5,Ws7)
        do_node(g_state[5], nullptr, Ws + 5 * WSZ, g_state[5], g_state[6], 2, 16, mrow0, c0, smA, smB, macc);
        do_node(g_state[5], nullptr, Ws + 7 * WSZ, g_state[5], g_state[8], 1, 16, mrow0, c0, smA, smB, macc);

        // mean of s1..s8 -> hiddens[t], g_h (and h_last at t=TT-1)
        int colg = c0 + (cg << 2);
#pragma unroll
        for (int r = 0; r < 2; r++) {
            int row = mrow0 + (rg << 1) + r;
            float4 mv = make_float4(macc[r*4+0] * 0.125f, macc[r*4+1] * 0.125f,
                                    macc[r*4+2] * 0.125f, macc[r*4+3] * 0.125f);
            __stcg((float4*)(g_h + (size_t)row * NH + colg), mv);
            *(float4*)(out + (size_t)t * BB * NH + (size_t)row * NH + colg) = mv;
            if (t == TT - 1)
                *(float4*)(out + (size_t)TT * BB * NH + (size_t)row * NH + colg) = mv;
        }
        gbar(sense);                            // publish g_h for next step
    }
}

__global__ void rnn_init(const float* __restrict__ hidden) {
    int i = blockIdx.x * blockDim.x + threadIdx.x;
    if (i < BB * NH) g_h[i] = hidden[i];
    if (i == 0) { g_count = 0u; g_sense = 0u; }
}

extern "C" void kernel_launch(void* const* d_in, const int* in_sizes, int n_in,
                              void* d_out, int out_size) {
    (void)in_sizes; (void)n_in; (void)out_size;
    const float* x   = (const float*)d_in[0];   // [400,256,512]
    const float* hid = (const float*)d_in[1];   // [1,256,512]
    const float* W0  = (const float*)d_in[2];   // [1024,1024]
    const float* Ws  = (const float*)d_in[3];   // [8,512,1024]
    float* out = (float*)d_out;                 // hiddens ++ h_last

    rnn_init<<<(BB * NH + 255) / 256, 256>>>(hid);
    rnn_persist<<<NCTA, NTHR>>>(x, W0, Ws, out);
}

// round 14
// speedup vs baseline: 1.3746x; 1.0138x over previous
#include <cuda_runtime.h>
#include <cstdint>
#include <cstddef>

// ---------------------------------------------------------------------------
// DARTS-RNN persistent kernel, fp32, FFMA2 inner product, v3.
// 256 CTAs = 8 M-tiles(32 rows) x 32 col-tiles(16 s-cols); 128 threads/CTA;
// 2 CTAs per SM (2 warps/SMSP) for latency hiding. Thread tile 2 rows x
// 2 s-cols (8 GEMM outputs, 4 f32x2 accumulators). A transposed in smem,
// B natural in smem, A-dup via ALU movs. One __syncthreads per K-chunk.
// Grid barrier between DAG levels.
// ---------------------------------------------------------------------------

#define TT    400
#define BB    256
#define NH    512
#define NCTA  256
#define NTHR  128
#define KT    32
#define MRWS  32           // rows per CTA tile
#define APAD  34           // As[k][row(32)+pad]; 136B row stride (8B mult)
#define BPAD  36           // Bs[k][col(32)+pad]; 144B row stride (16B mult)
#define WSZ   (512*1024)

typedef unsigned long long u64;

__device__ float    g_state[9][BB * NH];   // s0..s8
__device__ float    g_h[BB * NH];          // h_prev
__device__ unsigned g_count;
__device__ unsigned g_sense;

// ---- packed f32x2 helpers -------------------------------------------------
__device__ __forceinline__ u64 f2fma(u64 a, u64 b, u64 c) {
    u64 d;
    asm("fma.rn.f32x2 %0, %1, %2, %3;" : "=l"(d) : "l"(a), "l"(b), "l"(c));
    return d;
}
__device__ __forceinline__ u64 dup2(float x) {
    u64 d;
    asm("mov.b64 %0, {%1, %1};" : "=l"(d) : "f"(x));
    return d;
}
__device__ __forceinline__ void upk2(u64 v, float& x, float& y) {
    asm("mov.b64 {%0,%1}, %2;" : "=f"(x), "=f"(y) : "l"(v));
}

// ---- grid barrier (sense-reversing; init kernel resets state) -------------
__device__ __forceinline__ void gbar(unsigned& sense) {
    __syncthreads();
    if (threadIdx.x == 0) {
        sense ^= 1u;
        __threadfence();
        if (atomicAdd(&g_count, 1u) == NCTA - 1u) {
            atomicExch(&g_count, 0u);
            __threadfence();
            atomicExch(&g_sense, sense);
        } else {
            while (*((volatile unsigned*)&g_sense) != sense) { }
        }
        __threadfence();
    }
    __syncthreads();
}

// ---- staging --------------------------------------------------------------
// A: 32 rows x KT k (row-major global, stride 512) -> As[k][row] transposed.
// B: KT k x 32 cols (16 c-cols at c0, 16 h-cols at 512+c0) -> Bs[k][0..31].
__device__ __forceinline__ void stage_load(
    const float* __restrict__ A1, const float* __restrict__ A2,
    const float* __restrict__ W,
    int mrow0, int c0, int k0, int tid,
    float4 pa[2], float4 pb[2])
{
    const float* base = A1;
    int kk0 = k0;
    if (A2 != nullptr && k0 >= 512) { base = A2; kk0 = k0 - 512; }
#pragma unroll
    for (int i = 0; i < 2; i++) {
        int fid = tid + i * NTHR;              // 0..255
        int r = fid >> 3, k4 = fid & 7;        // r 0..31, k4 0..7
        pa[i] = __ldcg((const float4*)(base + (size_t)(mrow0 + r) * 512 + kk0 + (k4 << 2)));
    }
#pragma unroll
    for (int i = 0; i < 2; i++) {
        int fid = tid + i * NTHR;              // 0..255
        int kk = fid >> 3, q = fid & 7;
        int col = (q < 4) ? (c0 + (q << 2)) : (512 + c0 + ((q - 4) << 2));
        pb[i] = __ldg((const float4*)(W + (size_t)(k0 + kk) * 1024 + col));
    }
}

__device__ __forceinline__ void stage_store(
    const float4 pa[2], const float4 pb[2], int tid,
    float (*As)[APAD], float (*Bs)[BPAD])
{
#pragma unroll
    for (int i = 0; i < 2; i++) {
        int fid = tid + i * NTHR;
        int r = fid >> 3, k4 = fid & 7;
        As[(k4 << 2) + 0][r] = pa[i].x;
        As[(k4 << 2) + 1][r] = pa[i].y;
        As[(k4 << 2) + 2][r] = pa[i].z;
        As[(k4 << 2) + 3][r] = pa[i].w;
    }
#pragma unroll
    for (int i = 0; i < 2; i++) {
        int fid = tid + i * NTHR;
        int kk = fid >> 3, q = fid & 7;
        *(float4*)&Bs[kk][q << 2] = pb[i];     // local col 4q (c: q<4, h: q>=4)
    }
}

// inner product: acc = {row0xc-pair, row0xh-pair, row1xc-pair, row1xh-pair}
// for thread rows {2rg,2rg+1} and s-cols {2cg,2cg+1}.
__device__ __forceinline__ void compute_chunk(
    const float (*As)[APAD], const float (*Bs)[BPAD],
    int rg, int cg, u64 acc[4])
{
#pragma unroll 8
    for (int k = 0; k < KT; k++) {
        float2 av = *(const float2*)&As[k][rg << 1];        // rows 2rg,2rg+1
        u64 bc = *(const u64*)&Bs[k][cg << 1];              // c cols 2cg,2cg+1
        u64 bh = *(const u64*)&Bs[k][16 + (cg << 1)];       // h cols
        u64 a0 = dup2(av.x), a1 = dup2(av.y);
        acc[0] = f2fma(a0, bc, acc[0]);
        acc[1] = f2fma(a0, bh, acc[1]);
        acc[2] = f2fma(a1, bc, acc[2]);
        acc[3] = f2fma(a1, bh, acc[3]);
    }
}

// act: 0=tanh 1=relu 2=sigmoid 3=identity
__device__ __forceinline__ float gate(int act, float c, float h, float sp) {
    float g = 1.0f / (1.0f + __expf(-c));
    float a;
    switch (act) {
        case 0:  a = tanhf(h); break;
        case 1:  a = fmaxf(h, 0.0f); break;
        case 2:  a = 1.0f / (1.0f + __expf(-h)); break;
        default: a = h; break;
    }
    return sp + g * (a - sp);
}

// One DAG node: SD = SP + sigmoid(c) * (act(h) - SP), [c|h] = A @ W.
__device__ __forceinline__ void do_node(
    const float* __restrict__ A1, const float* __restrict__ A2,
    const float* __restrict__ W,
    const float* __restrict__ SP, float* __restrict__ SD,
    int act, int nchunk, int mrow0, int c0,
    float (*smA)[KT][APAD], float (*smB)[KT][BPAD],
    float* macc)
{
    int tid = threadIdx.x;
    int cg = tid & 7, rg = tid >> 3;           // 8 col-groups x 16 row-groups
    u64 acc[4] = {0,0,0,0};
    float4 pa[2]; float4 pb[2];

    stage_load(A1, A2, W, mrow0, c0, 0, tid, pa, pb);
    __syncthreads();                            // retire prev node's smem reads
    stage_store(pa, pb, tid, smA[0], smB[0]);

#pragma unroll 1
    for (int ch = 0; ch < nchunk; ch++) {
        if (ch + 1 < nchunk)
            stage_load(A1, A2, W, mrow0, c0, (ch + 1) * KT, tid, pa, pb);
        __syncthreads();                        // buf[ch] visible; buf[ch+1] free
        if (ch + 1 < nchunk)
            stage_store(pa, pb, tid, smA[(ch + 1) & 1], smB[(ch + 1) & 1]);
        compute_chunk(smA[ch & 1], smB[ch & 1], rg, cg, acc);
    }

    // epilogue: rows {2rg,2rg+1}, s-cols {c0+2cg, c0+2cg+1}
    float cv[2][2], hv[2][2];
    upk2(acc[0], cv[0][0], cv[0][1]);
    upk2(acc[1], hv[0][0], hv[0][1]);
    upk2(acc[2], cv[1][0], cv[1][1]);
    upk2(acc[3], hv[1][0], hv[1][1]);
    int colg = c0 + (cg << 1);
#pragma unroll
    for (int r = 0; r < 2; r++) {
        int row = mrow0 + (rg << 1) + r;
        float2 sp = __ldcg((const float2*)(SP + (size_t)row * NH + colg));
        float2 v;
        v.x = gate(act, cv[r][0], hv[r][0], sp.x);
        v.y = gate(act, cv[r][1], hv[r][1], sp.y);
        __stcg((float2*)(SD + (size_t)row * NH + colg), v);
        if (macc) { macc[r * 2 + 0] += v.x; macc[r * 2 + 1] += v.y; }
    }
}

// ---------------------------------------------------------------------------
__global__ void __launch_bounds__(NTHR, 2)
rnn_persist(const float* __restrict__ x,
            const float* __restrict__ W0,
            const float* __restrict__ Ws,
            float* __restrict__ out)
{
    __shared__ __align__(16) float smA[2][KT][APAD];
    __shared__ __align__(16) float smB[2][KT][BPAD];

    int bid = blockIdx.x;
    int mrow0 = (bid >> 5) * MRWS;             // 8 M-tiles of 32 rows
    int c0 = (bid & 31) * 16;                  // 32 col-tiles of 16 s-cols
    int tid = threadIdx.x;
    int cg = tid & 7, rg = tid >> 3;
    unsigned sense = 0;

#pragma unroll 1
    for (int t = 0; t < TT; t++) {
        const float* xt = x + (size_t)t * BB * NH;
        float macc[4] = {0.f,0.f,0.f,0.f};

        // s0: [c|h] = concat(x_t, h_prev) @ W0, gate vs h_prev (tanh)
        do_node(xt, g_h, W0, g_h, g_state[0], 0, 32, mrow0, c0, smA, smB, nullptr);
        gbar(sense);
        // L1: s1 = tanh-node(s0, Ws0)
        do_node(g_state[0], nullptr, Ws + 0 * WSZ, g_state[0], g_state[1], 0, 16, mrow0, c0, smA, smB, macc);
        gbar(sense);
        // L2: s2=relu(s1,Ws1), s3=relu(s1,Ws2), s4=id(s1,Ws3)
        do_node(g_state[1], nullptr, Ws + 1 * WSZ, g_state[1], g_state[2], 1, 16, mrow0, c0, smA, smB, macc);
        do_node(g_state[1], nullptr, Ws + 2 * WSZ, g_state[1], g_state[3], 1, 16, mrow0, c0, smA, smB, macc);
        do_node(g_state[1], nullptr, Ws + 3 * WSZ, g_state[1], g_state[4], 3, 16, mrow0, c0, smA, smB, macc);
        gbar(sense);
        // L3: s5=tanh(s2,Ws4), s7=tanh(s3,Ws6)
        do_node(g_state[2], nullptr, Ws + 4 * WSZ, g_state[2], g_state[5], 0, 16, mrow0, c0, smA, smB, macc);
        do_node(g_state[3], nullptr, Ws + 6 * WSZ, g_state[3], g_state[7], 0, 16, mrow0, c0, smA, smB, macc);
        gbar(sense);
        // L4: s6=sigmoid(s5,Ws5), s8=relu(s5,Ws7)
        do_node(g_state[5], nullptr, Ws + 5 * WSZ, g_state[5], g_state[6], 2, 16, mrow0, c0, smA, smB, macc);
        do_node(g_state[5], nullptr, Ws + 7 * WSZ, g_state[5], g_state[8], 1, 16, mrow0, c0, smA, smB, macc);

        // mean of s1..s8 -> hiddens[t], g_h (and h_last at t=TT-1)
        int colg = c0 + (cg << 1);
#pragma unroll
        for (int r = 0; r < 2; r++) {
            int row = mrow0 + (rg << 1) + r;
            float2 mv = make_float2(macc[r*2+0] * 0.125f, macc[r*2+1] * 0.125f);
            __stcg((float2*)(g_h + (size_t)row * NH + colg), mv);
            *(float2*)(out + (size_t)t * BB * NH + (size_t)row * NH + colg) = mv;
            if (t == TT - 1)
                *(float2*)(out + (size_t)TT * BB * NH + (size_t)row * NH + colg) = mv;
        }
        gbar(sense);                            // publish g_h for next step
    }
}

__global__ void rnn_init(const float* __restrict__ hidden) {
    int i = blockIdx.x * blockDim.x + threadIdx.x;
    if (i < BB * NH) g_h[i] = hidden[i];
    if (i == 0) { g_count = 0u; g_sense = 0u; }
}

extern "C" void kernel_launch(void* const* d_in, const int* in_sizes, int n_in,
                              void* d_out, int out_size) {
    (void)in_sizes; (void)n_in; (void)out_size;
    const float* x   = (const float*)d_in[0];   // [400,256,512]
    const float* hid = (const float*)d_in[1];   // [1,256,512]
    const float* W0  = (const float*)d_in[2];   // [1024,1024]
    const float* Ws  = (const float*)d_in[3];   // [8,512,1024]
    float* out = (float*)d_out;                 // hiddens ++ h_last

    rnn_init<<<(BB * NH + 255) / 256, 256>>>(hid);
    rnn_persist<<<NCTA, NTHR>>>(x, W0, Ws, out);
}